// round 1
// baseline (speedup 1.0000x reference)
#include <cuda_runtime.h>
#include <math.h>

#define N      4096
#define D      128
#define NW     128          // 4096 bits / 32 = 128 words per bitset row
#define RPB    16           // rows per GEMM block

// ---------------- scratch (device globals: no allocation allowed) ----------
__device__ unsigned  g_A [N * NW];   // 1-hop adjacency bitset
__device__ unsigned  g_A2[N * NW];   // unique 2-hop reachability
__device__ unsigned  g_A3[N * NW];   // unique 3-hop reachability
__device__ float     g_buf0[N * D];
__device__ float     g_buf1[N * D];
__device__ float     g_a0[N];
__device__ float     g_a1[N];
__device__ float     g_a2[N];
__device__ long long g_stepq[N];     // fixed-point hop-1 accumulator (deterministic)
__device__ float     g_step[N];
__device__ int       g_is64;

// ---------------- zero init -------------------------------------------------
__global__ void zero_kernel() {
    int i = blockIdx.x * blockDim.x + threadIdx.x;
    if (i < N * NW) g_A[i] = 0u;
    if (i < N)      g_stepq[i] = 0ll;
}

// ---------------- GEMM: Y[r][c] = relu( sum_k X[r][k]*W[c][k] + b[c] ) ------
// 128 threads, 16 rows/block, 4x4 register tile per thread.
// smem: Wt[k][c] padded 132, Xt[k][r] padded 20.
__global__ __launch_bounds__(128, 2)
void gemm_relu_kernel(const float* __restrict__ Xext,
                      const float* __restrict__ W,
                      const float* __restrict__ bias,
                      int src, int dst) {
    extern __shared__ float sm[];
    float* Wt = sm;                 // 128*132
    float* Xt = sm + 128 * 132;     // 128*20

    const float* X = (src == 0) ? Xext : (src == 1 ? g_buf0 : g_buf1);
    float*       Y = (dst == 1) ? g_buf0 : g_buf1;

    const int tid = threadIdx.x;
    const int r0  = blockIdx.x * RPB;

    // Wt[k*132 + c] = W[c*128 + k]   (c = i, k = tid)
    #pragma unroll 4
    for (int i = 0; i < 128; i++)
        Wt[tid * 132 + i] = W[i * 128 + tid];
    // Xt[k*20 + r] = X[(r0+r)*128 + k]
    #pragma unroll
    for (int i = 0; i < RPB; i++)
        Xt[tid * 20 + i] = X[(r0 + i) * 128 + tid];
    __syncthreads();

    const int cq = tid & 31;   // 32 column groups of 4
    const int rq = tid >> 5;   // 4 row groups of 4

    float acc[4][4];
    #pragma unroll
    for (int a = 0; a < 4; a++)
        #pragma unroll
        for (int b = 0; b < 4; b++) acc[a][b] = 0.f;

    #pragma unroll 4
    for (int k = 0; k < 128; k++) {
        float4 wv = *(const float4*)&Wt[k * 132 + cq * 4];
        float4 xv = *(const float4*)&Xt[k * 20  + rq * 4];
        float xs[4] = {xv.x, xv.y, xv.z, xv.w};
        float ws[4] = {wv.x, wv.y, wv.z, wv.w};
        #pragma unroll
        for (int rr = 0; rr < 4; rr++)
            #pragma unroll
            for (int cc = 0; cc < 4; cc++)
                acc[rr][cc] = fmaf(xs[rr], ws[cc], acc[rr][cc]);
    }

    #pragma unroll
    for (int rr = 0; rr < 4; rr++) {
        int r = r0 + rq * 4 + rr;
        float4 o;
        float b0 = bias ? bias[cq * 4 + 0] : 0.f;
        float b1 = bias ? bias[cq * 4 + 1] : 0.f;
        float b2 = bias ? bias[cq * 4 + 2] : 0.f;
        float b3 = bias ? bias[cq * 4 + 3] : 0.f;
        o.x = fmaxf(acc[rr][0] + b0, 0.f);
        o.y = fmaxf(acc[rr][1] + b1, 0.f);
        o.z = fmaxf(acc[rr][2] + b2, 0.f);
        o.w = fmaxf(acc[rr][3] + b3, 0.f);
        *(float4*)&Y[r * 128 + cq * 4] = o;
    }
}

// ---------------- final layer: a[r] = dot(H[r], W3) + b3 --------------------
__global__ void final_dot_kernel(const float* __restrict__ W3,
                                 const float* __restrict__ b3) {
    int gw   = (blockIdx.x * blockDim.x + threadIdx.x) >> 5;
    int lane = threadIdx.x & 31;
    if (gw >= N) return;
    const float* h = g_buf0 + gw * 128;   // last relu output lives in buf0
    float s = h[lane]      * W3[lane]
            + h[lane + 32] * W3[lane + 32]
            + h[lane + 64] * W3[lane + 64]
            + h[lane + 96] * W3[lane + 96];
    #pragma unroll
    for (int o = 16; o; o >>= 1) s += __shfl_down_sync(0xffffffffu, s, o);
    if (lane == 0) g_a0[gw] = s + b3[0];
}

// ---------------- dtype detection: is edge_index really int64? --------------
__global__ void detect_kernel(const void* ei) {
    const long long* p = (const long long*)ei;
    __shared__ int bad;
    if (threadIdx.x == 0) bad = 0;
    __syncthreads();
    for (int i = threadIdx.x; i < 2048; i += blockDim.x) {
        long long v = p[i];
        if (v < 0 || v >= N) bad = 1;
    }
    __syncthreads();
    if (threadIdx.x == 0) g_is64 = bad ? 0 : 1;
}

// ---------------- edges: bitset build + hop-1 scatter (duplicates kept) -----
__global__ void edge_kernel(const void* __restrict__ ei, int ne) {
    int e = blockIdx.x * blockDim.x + threadIdx.x;
    if (e >= ne) return;
    int row, col;
    if (g_is64) {
        const long long* p = (const long long*)ei;
        row = (int)p[e];
        col = (int)p[ne + e];
    } else {
        const int* p = (const int*)ei;
        row = p[e];
        col = p[ne + e];
    }
    atomicOr(&g_A[row * NW + (col >> 5)], 1u << (col & 31));
    float v = 0.69314718055994531f * g_a0[col];           // ln(2) * a0[col]
    long long q = __float2ll_rn(v * 4294967296.0f);       // 2^32 fixed point
    atomicAdd((unsigned long long*)&g_stepq[row], (unsigned long long)q);
}

__global__ void finish_hop1_kernel() {
    int i = blockIdx.x * blockDim.x + threadIdx.x;
    if (i >= N) return;
    float s = (float)((double)g_stepq[i] * (1.0 / 4294967296.0));
    g_step[i] = s;
    g_a1[i]   = g_a0[i] + s;
}

// ---------------- boolean matmul: Out[i] = OR_{j in A[i]} M[j] --------------
// which==0: M=g_A -> Out=g_A2 ; which==1: M=g_A2 -> Out=g_A3
__global__ __launch_bounds__(128)
void boolmm_kernel(int which) {
    const unsigned* M   = which ? g_A2 : g_A;
    unsigned*       Out = which ? g_A3 : g_A2;
    int i = blockIdx.x;
    int w = threadIdx.x;
    __shared__ unsigned srow[NW];
    srow[w] = g_A[i * NW + w];
    __syncthreads();
    unsigned acc = 0u;
    #pragma unroll 4
    for (int ww = 0; ww < NW; ww++) {
        unsigned m = srow[ww];
        int jb = ww * 32;
        while (m) {
            int b = __ffs((int)m) - 1;
            m &= m - 1;
            acc |= __ldg(&M[(jb + b) * NW + w]);
        }
    }
    Out[i * NW + w] = acc;
}

// ---------------- hop k>=2: s = Ak @ a_in ; step += c*s ; a_out = a_in+step -
// hop==2: Ak=g_A2, a_in=g_a1, a_out=g_a2, c=ln3
// hop==3: Ak=g_A3, a_in=g_a2, a_out=out  , c=ln4
__global__ __launch_bounds__(128)
void hop_kernel(int hop, float* __restrict__ out_final) {
    const unsigned* Ak   = (hop == 2) ? g_A2 : g_A3;
    const float*    a_in = (hop == 2) ? g_a1 : g_a2;
    float*          a_out= (hop == 2) ? g_a2 : out_final;
    const float     coef = (hop == 2) ? 1.0986122886681098f : 1.3862943611198906f;

    int i = blockIdx.x;
    int w = threadIdx.x;
    unsigned m = Ak[i * NW + w];
    const float* base = a_in + w * 32;
    float s = 0.f;
    while (m) {
        int b = __ffs((int)m) - 1;
        m &= m - 1;
        s += __ldg(&base[b]);
    }
    #pragma unroll
    for (int o = 16; o; o >>= 1) s += __shfl_down_sync(0xffffffffu, s, o);
    __shared__ float part[4];
    if ((w & 31) == 0) part[w >> 5] = s;
    __syncthreads();
    if (w == 0) {
        float tot = part[0] + part[1] + part[2] + part[3];
        float ns  = g_step[i] + coef * tot;
        g_step[i] = ns;
        a_out[i]  = a_in[i] + ns;
    }
}

// ---------------- launch ----------------------------------------------------
extern "C" void kernel_launch(void* const* d_in, const int* in_sizes, int n_in,
                              void* d_out, int out_size) {
    const float* coeffs = (const float*)d_in[0];
    const void*  ei     = d_in[1];
    const float* W0     = (const float*)d_in[2];
    const float* b0     = (const float*)d_in[3];
    const float* W1     = (const float*)d_in[4];
    const float* W2     = (const float*)d_in[5];
    const float* W3     = (const float*)d_in[6];
    const float* b3     = (const float*)d_in[7];
    float* out = (float*)d_out;

    const int ne = in_sizes[1] / 2;
    const int smem = (128 * 132 + 128 * 20) * (int)sizeof(float);  // 77824 B

    cudaFuncSetAttribute(gemm_relu_kernel,
                         cudaFuncAttributeMaxDynamicSharedMemorySize, smem);

    // init
    zero_kernel<<<(N * NW + 255) / 256, 256>>>();

    // MLP
    gemm_relu_kernel<<<N / RPB, 128, smem>>>(coeffs, W0, b0, 0, 1); // coeffs->buf0
    gemm_relu_kernel<<<N / RPB, 128, smem>>>(nullptr, W1, nullptr, 1, 2); // buf0->buf1
    gemm_relu_kernel<<<N / RPB, 128, smem>>>(nullptr, W2, nullptr, 2, 1); // buf1->buf0
    final_dot_kernel<<<(N * 32 + 255) / 256, 256>>>(W3, b3);             // buf0->a0

    // graph
    detect_kernel<<<1, 256>>>(ei);
    edge_kernel<<<(ne + 255) / 256, 256>>>(ei, ne);
    finish_hop1_kernel<<<(N + 255) / 256, 256>>>();

    boolmm_kernel<<<N, 128>>>(0);   // A2 = A (.) A
    boolmm_kernel<<<N, 128>>>(1);   // A3 = A (.) A2

    hop_kernel<<<N, 128>>>(2, out);
    hop_kernel<<<N, 128>>>(3, out);
}

// round 2
// speedup vs baseline: 1.1253x; 1.1253x over previous
#include <cuda_runtime.h>
#include <math.h>

#define N      4096
#define D      128
#define NW     128          // 4096 bits / 32
#define RPB    16           // rows per GEMM block

// ---------------- scratch (device globals) ----------------------------------
__device__ unsigned  g_A  [N * NW];   // 1-hop adjacency bitset
__device__ unsigned  g_A2 [N * NW];   // unique 2-hop reachability
__device__ float     g_Wt [3 * D * D]; // pre-transposed weights, k-major
__device__ float     g_buf0[N * D];
__device__ float     g_buf1[N * D];
__device__ float     g_a0[N];
__device__ float     g_a1[N];
__device__ float     g_av2[N];
__device__ long long g_stepq[N];      // fixed-point hop-1 accumulator
__device__ float     g_step[N];
__device__ int       g_is64;

#define FMA2(acc, w, x) asm("fma.rn.f32x2 %0, %1, %2, %0;" : "+l"(acc) : "l"(w), "l"(x))

union U64F2 { unsigned long long u; float2 f; };

// ---------------- prep: zero A/stepq + transpose W0..W2 + dtype detect ------
__global__ void prep_kernel(const float* __restrict__ W0,
                            const float* __restrict__ W1,
                            const float* __restrict__ W2,
                            const void* __restrict__ ei) {
    if (blockIdx.x == gridDim.x - 1) {           // dtype detection block
        __shared__ int bad;
        if (threadIdx.x == 0) bad = 0;
        __syncthreads();
        const long long* p = (const long long*)ei;
        for (int i = threadIdx.x; i < 2048; i += blockDim.x) {
            long long v = p[i];
            if (v < 0 || v >= N) bad = 1;
        }
        __syncthreads();
        if (threadIdx.x == 0) g_is64 = bad ? 0 : 1;
        return;
    }
    int idx = blockIdx.x * 256 + threadIdx.x;
    if (idx < N * NW) {
        g_A[idx] = 0u;
        if (idx < N) g_stepq[idx] = 0ll;
    } else {
        int t = idx - N * NW;                    // < 3*16384 by grid sizing
        int m  = t >> 14;
        int tp = t & 16383;                      // tp = k*128 + c
        int c  = tp & 127;
        int k  = tp >> 7;
        const float* Ws = (m == 0) ? W0 : (m == 1 ? W1 : W2);
        g_Wt[m * 16384 + tp] = Ws[c * 128 + k];
    }
}

// ---------------- GEMM: Y = relu(X @ W^T (+b)); optional fused W3 dot -------
// 256 threads, 16 rows/block, thread tile 1 row x 8 cols (4 x f32x2).
// smem: Wt[k][c] stride 132 (full 128x128), Xt[r][k] stride 132.
__global__ __launch_bounds__(256, 2)
void gemm_kernel(const float* __restrict__ X,
                 const float* __restrict__ Wg,
                 const float* __restrict__ bias,
                 float* __restrict__ Y,
                 const float* __restrict__ W3,     // non-null => fused final dot
                 const float* __restrict__ b3) {
    extern __shared__ float sm[];
    float* Wt = sm;                  // 128*132
    float* Xt = sm + 128 * 132;      // 16*132

    const int tid = threadIdx.x;
    const int r0  = blockIdx.x * RPB;

    // stage W (k-major, conflict-free float4)
    #pragma unroll
    for (int it = 0; it < 16; it++) {
        int idx = it * 256 + tid;
        int k = idx >> 5, c4 = idx & 31;
        *(float4*)&Wt[k * 132 + c4 * 4] = *(const float4*)&Wg[k * 128 + c4 * 4];
    }
    // stage X rows (row-major, stride 132)
    #pragma unroll
    for (int it = 0; it < 2; it++) {
        int idx = it * 256 + tid;
        int r = idx >> 5, k4 = idx & 31;
        *(float4*)&Xt[r * 132 + k4 * 4] = *(const float4*)&X[(r0 + r) * 128 + k4 * 4];
    }
    __syncthreads();

    const int cg = tid & 15;    // 16 col-groups of 8
    const int r  = tid >> 4;    // 16 rows

    unsigned long long acc0 = 0, acc1 = 0, acc2 = 0, acc3 = 0;
    const float* xrow  = Xt + r * 132;
    const float* wbase = Wt + cg * 8;

    #pragma unroll 8
    for (int k = 0; k < 128; k++) {
        float xv = xrow[k];
        unsigned long long x2;
        asm("mov.b64 %0, {%1, %1};" : "=l"(x2) : "f"(xv));
        const float* wp = wbase + k * 132;
        ulonglong2 wa = *(const ulonglong2*)wp;
        ulonglong2 wb = *(const ulonglong2*)(wp + 4);
        FMA2(acc0, wa.x, x2);
        FMA2(acc1, wa.y, x2);
        FMA2(acc2, wb.x, x2);
        FMA2(acc3, wb.y, x2);
    }

    U64F2 u0, u1, u2, u3;
    u0.u = acc0; u1.u = acc1; u2.u = acc2; u3.u = acc3;
    float o[8] = {u0.f.x, u0.f.y, u1.f.x, u1.f.y, u2.f.x, u2.f.y, u3.f.x, u3.f.y};

    if (bias) {
        #pragma unroll
        for (int j = 0; j < 8; j++) o[j] += bias[cg * 8 + j];
    }
    #pragma unroll
    for (int j = 0; j < 8; j++) o[j] = fmaxf(o[j], 0.f);

    if (!W3) {
        float4 v0 = {o[0], o[1], o[2], o[3]};
        float4 v1 = {o[4], o[5], o[6], o[7]};
        *(float4*)&Y[(r0 + r) * 128 + cg * 8]     = v0;
        *(float4*)&Y[(r0 + r) * 128 + cg * 8 + 4] = v1;
    } else {
        // fused final layer: a0[row] = dot(relu_out, W3) + b3
        float p = 0.f;
        #pragma unroll
        for (int j = 0; j < 8; j++) p = fmaf(o[j], W3[cg * 8 + j], p);
        #pragma unroll
        for (int off = 8; off; off >>= 1)
            p += __shfl_down_sync(0xffffffffu, p, off, 16);
        if (cg == 0) g_a0[r0 + r] = p + b3[0];
    }
}

// ---------------- edges: bitset build + hop-1 scatter (duplicates kept) -----
__global__ void edge_kernel(const void* __restrict__ ei, int ne) {
    int e = blockIdx.x * blockDim.x + threadIdx.x;
    if (e >= ne) return;
    int row, col;
    if (g_is64) {
        const long long* p = (const long long*)ei;
        row = (int)p[e];
        col = (int)p[ne + e];
    } else {
        const int* p = (const int*)ei;
        row = p[e];
        col = p[ne + e];
    }
    atomicOr(&g_A[row * NW + (col >> 5)], 1u << (col & 31));
    float v = 0.69314718055994531f * g_a0[col];           // ln(2) * a0[col]
    long long q = __float2ll_rn(v * 4294967296.0f);       // 2^32 fixed point
    atomicAdd((unsigned long long*)&g_stepq[row], (unsigned long long)q);
}

__global__ void finish_hop1_kernel() {
    int i = blockIdx.x * blockDim.x + threadIdx.x;
    if (i >= N) return;
    float s = (float)((double)g_stepq[i] * (1.0 / 4294967296.0));
    g_step[i] = s;
    g_a1[i]   = g_a0[i] + s;
}

// ---------------- fused boolmm + gated matvec --------------------------------
// phase 0: A2row = OR_{j in A[i]} A[j];  s = sum bits(A2row) of a1;
//          step += ln3*s; av2 = a1 + step; store A2row.
// phase 1: A3row = OR_{j in A[i]} A2[j]; s = sum bits(A3row) of av2;
//          out = av2 + step + ln4*s.   (A3 never materialized)
__global__ __launch_bounds__(128)
void fused_hop_kernel(int phase, float* __restrict__ out_final) {
    const unsigned* M   = phase ? g_A2  : g_A;
    const float*    vec = phase ? g_av2 : g_a1;

    const int i = blockIdx.x;
    const int w = threadIdx.x;

    __shared__ unsigned short list[4096];
    __shared__ int cnt;
    __shared__ float part[4];
    if (w == 0) cnt = 0;
    __syncthreads();

    // extract neighbor list of row i into smem
    unsigned m0 = g_A[i * NW + w];
    int nb = __popc(m0);
    int pos = nb ? atomicAdd(&cnt, nb) : 0;
    {
        unsigned mt = m0;
        int jb = w * 32;
        while (mt) {
            int b = __ffs((int)mt) - 1;
            mt &= mt - 1;
            list[pos++] = (unsigned short)(jb + b);
        }
    }
    __syncthreads();

    const int c = cnt;
    unsigned acc = 0u;
    int j = 0;
    for (; j + 4 <= c; j += 4) {
        unsigned q0 = __ldg(&M[(int)list[j]     * NW + w]);
        unsigned q1 = __ldg(&M[(int)list[j + 1] * NW + w]);
        unsigned q2 = __ldg(&M[(int)list[j + 2] * NW + w]);
        unsigned q3 = __ldg(&M[(int)list[j + 3] * NW + w]);
        acc |= (q0 | q1) | (q2 | q3);
    }
    for (; j < c; j++) acc |= __ldg(&M[(int)list[j] * NW + w]);

    if (!phase) g_A2[i * NW + w] = acc;

    // gated sum of vec over set bits
    float s = 0.f;
    {
        const float* base = vec + w * 32;
        unsigned m = acc;
        while (m) {
            int b = __ffs((int)m) - 1;
            m &= m - 1;
            s += base[b];
        }
    }
    #pragma unroll
    for (int o = 16; o; o >>= 1) s += __shfl_down_sync(0xffffffffu, s, o);
    if ((w & 31) == 0) part[w >> 5] = s;
    __syncthreads();
    if (w == 0) {
        float tot = part[0] + part[1] + part[2] + part[3];
        if (!phase) {
            float ns = g_step[i] + 1.0986122886681098f * tot;   // ln 3
            g_step[i] = ns;
            g_av2[i]  = vec[i] + ns;
        } else {
            out_final[i] = vec[i] + g_step[i] + 1.3862943611198906f * tot; // ln 4
        }
    }
}

// ---------------- launch ----------------------------------------------------
extern "C" void kernel_launch(void* const* d_in, const int* in_sizes, int n_in,
                              void* d_out, int out_size) {
    const float* coeffs = (const float*)d_in[0];
    const void*  ei     = d_in[1];
    const float* W0     = (const float*)d_in[2];
    const float* b0     = (const float*)d_in[3];
    const float* W1     = (const float*)d_in[4];
    const float* W2     = (const float*)d_in[5];
    const float* W3     = (const float*)d_in[6];
    const float* b3     = (const float*)d_in[7];
    float* out = (float*)d_out;

    const int ne   = in_sizes[1] / 2;
    const int smem = (128 * 132 + 16 * 132) * (int)sizeof(float);  // 76032 B

    static int attr_set = 0;
    cudaFuncSetAttribute(gemm_kernel,
                         cudaFuncAttributeMaxDynamicSharedMemorySize, smem);
    (void)attr_set;

    float* Wt0; cudaGetSymbolAddress((void**)&Wt0, g_Wt);
    float* Wt1 = Wt0 + 16384;
    float* Wt2 = Wt0 + 32768;
    float* b0d; cudaGetSymbolAddress((void**)&b0d, g_buf0);
    float* b1d; cudaGetSymbolAddress((void**)&b1d, g_buf1);

    const int prep_blocks = (N * NW + 3 * 16384) / 256 + 1;  // 2240 work + 1 detect
    prep_kernel<<<prep_blocks, 256>>>(W0, W1, W2, ei);

    gemm_kernel<<<N / RPB, 256, smem>>>(coeffs, Wt0, b0,      b1d, nullptr, nullptr);
    gemm_kernel<<<N / RPB, 256, smem>>>(b1d,    Wt1, nullptr, b0d, nullptr, nullptr);
    gemm_kernel<<<N / RPB, 256, smem>>>(b0d,    Wt2, nullptr, nullptr, W3,  b3);

    edge_kernel<<<(ne + 255) / 256, 256>>>(ei, ne);
    finish_hop1_kernel<<<(N + 255) / 256, 256>>>();

    fused_hop_kernel<<<N, 128>>>(0, out);
    fused_hop_kernel<<<N, 128>>>(1, out);
}

// round 3
// speedup vs baseline: 2.1651x; 1.9240x over previous
#include <cuda_runtime.h>
#include <math.h>

#define N      4096
#define D      128
#define NW     128          // 4096 bits / 32
#define GEMM_R 32           // rows per GEMM block
#define HOP_G  8            // rows per hop block
#define LISTCAP 2048

// ---------------- scratch (device globals) ----------------------------------
__device__ unsigned  g_A  [N * NW];
__device__ unsigned  g_A2 [N * NW];
__device__ float     g_Wt [3 * D * D];   // pre-transposed weights, k-major
__device__ float     g_buf0[N * D];
__device__ float     g_buf1[N * D];
__device__ float     g_a0[N];
__device__ float     g_a1[N];
__device__ float     g_av2[N];
__device__ long long g_stepq[N];
__device__ float     g_step[N];
__device__ int       g_is64;

#define FMA2(acc, w, x) asm("fma.rn.f32x2 %0, %1, %2, %0;" : "+l"(acc) : "l"(w), "l"(x))
#define BCAST2(dst, s)  asm("mov.b64 %0, {%1, %1};" : "=l"(dst) : "f"(s))
union U64F2 { unsigned long long u; float2 f; };

// ---------------- prep: zero A/stepq + transpose W0..W2 + dtype detect ------
__global__ void prep_kernel(const float* __restrict__ W0,
                            const float* __restrict__ W1,
                            const float* __restrict__ W2,
                            const void* __restrict__ ei) {
    if (blockIdx.x == gridDim.x - 1) {
        __shared__ int bad;
        if (threadIdx.x == 0) bad = 0;
        __syncthreads();
        const long long* p = (const long long*)ei;
        for (int i = threadIdx.x; i < 2048; i += blockDim.x) {
            long long v = p[i];
            if (v < 0 || v >= N) bad = 1;
        }
        __syncthreads();
        if (threadIdx.x == 0) g_is64 = bad ? 0 : 1;
        return;
    }
    int idx = blockIdx.x * 256 + threadIdx.x;
    if (idx < N * NW) {
        g_A[idx] = 0u;
        if (idx < N) g_stepq[idx] = 0ll;
    } else {
        int t = idx - N * NW;
        int m  = t >> 14;
        int tp = t & 16383;                  // tp = k*128 + c
        int c  = tp & 127;
        int k  = tp >> 7;
        const float* Ws = (m == 0) ? W0 : (m == 1 ? W1 : W2);
        g_Wt[m * 16384 + tp] = Ws[c * 128 + k];
    }
}

// ---------------- GEMM: Y = relu(X @ W^T (+b)); optional fused W3 dot -------
// 256 threads; block tile 32 rows x 128 cols; thread tile 4 rows x 4 cols.
// Wt smem [k][c] stride 132 ; Xt smem [k][r] stride 36 (both k-major).
__global__ __launch_bounds__(256, 1)
void gemm_kernel(const float* __restrict__ X,
                 const float* __restrict__ Wg,
                 const float* __restrict__ bias,
                 float* __restrict__ Y,
                 const float* __restrict__ W3,
                 const float* __restrict__ b3) {
    extern __shared__ float sm[];
    float* Wt = sm;                  // 128*132 = 67584 B
    float* Xt = sm + 128 * 132;      // 128*36  = 18432 B

    const int tid = threadIdx.x;
    const int r0  = blockIdx.x * GEMM_R;
    const int cg  = tid & 31;        // col group of 4 (lane)
    const int rq  = tid >> 5;        // row group of 4 (warp)

    // stage W: k-major float4, conflict-free
    #pragma unroll
    for (int it = 0; it < 16; it++) {
        int idx = it * 256 + tid;
        int k = idx >> 5, c4 = idx & 31;
        *(float4*)&Wt[k * 132 + c4 * 4] = *(const float4*)&Wg[k * 128 + c4 * 4];
    }
    // stage X transposed: Xt[k][r]; lanes vary r -> conflict-free stores
    #pragma unroll
    for (int it = 0; it < 4; it++) {
        int idx = it * 256 + tid;
        int kc = idx >> 5, r = idx & 31;
        float4 xv = *(const float4*)&X[(r0 + r) * 128 + kc * 4];
        Xt[(kc * 4 + 0) * 36 + r] = xv.x;
        Xt[(kc * 4 + 1) * 36 + r] = xv.y;
        Xt[(kc * 4 + 2) * 36 + r] = xv.z;
        Xt[(kc * 4 + 3) * 36 + r] = xv.w;
    }
    __syncthreads();

    unsigned long long acc[4][2];
    #pragma unroll
    for (int r = 0; r < 4; r++) { acc[r][0] = 0ull; acc[r][1] = 0ull; }

    #pragma unroll 4
    for (int k = 0; k < 128; k++) {
        float4 xv = *(const float4*)&Xt[k * 36 + rq * 4];        // broadcast
        ulonglong2 wl = *(const ulonglong2*)&Wt[k * 132 + cg * 4];
        unsigned long long x2[4];
        BCAST2(x2[0], xv.x); BCAST2(x2[1], xv.y);
        BCAST2(x2[2], xv.z); BCAST2(x2[3], xv.w);
        #pragma unroll
        for (int r = 0; r < 4; r++) {
            FMA2(acc[r][0], wl.x, x2[r]);
            FMA2(acc[r][1], wl.y, x2[r]);
        }
    }

    float o[4][4];
    #pragma unroll
    for (int r = 0; r < 4; r++) {
        U64F2 u0, u1; u0.u = acc[r][0]; u1.u = acc[r][1];
        o[r][0] = u0.f.x; o[r][1] = u0.f.y; o[r][2] = u1.f.x; o[r][3] = u1.f.y;
    }
    if (bias) {
        float4 bv = *(const float4*)&bias[cg * 4];
        #pragma unroll
        for (int r = 0; r < 4; r++) {
            o[r][0] += bv.x; o[r][1] += bv.y; o[r][2] += bv.z; o[r][3] += bv.w;
        }
    }
    #pragma unroll
    for (int r = 0; r < 4; r++)
        #pragma unroll
        for (int c = 0; c < 4; c++) o[r][c] = fmaxf(o[r][c], 0.f);

    if (!W3) {
        #pragma unroll
        for (int r = 0; r < 4; r++) {
            float4 v = {o[r][0], o[r][1], o[r][2], o[r][3]};
            *(float4*)&Y[(r0 + rq * 4 + r) * 128 + cg * 4] = v;
        }
    } else {
        // fused final layer: a0[row] = dot(relu_out, W3) + b3
        float4 w3 = *(const float4*)&W3[cg * 4];
        #pragma unroll
        for (int r = 0; r < 4; r++) {
            float p = o[r][0] * w3.x + o[r][1] * w3.y + o[r][2] * w3.z + o[r][3] * w3.w;
            #pragma unroll
            for (int off = 16; off; off >>= 1)
                p += __shfl_down_sync(0xffffffffu, p, off);
            if (cg == 0) g_a0[r0 + rq * 4 + r] = p + b3[0];
        }
    }
}

// ---------------- edges: bitset build + hop-1 scatter (duplicates kept) -----
__global__ void edge_kernel(const void* __restrict__ ei, int ne) {
    int e = blockIdx.x * blockDim.x + threadIdx.x;
    if (e >= ne) return;
    int row, col;
    if (g_is64) {
        const long long* p = (const long long*)ei;
        row = (int)p[e];
        col = (int)p[ne + e];
    } else {
        const int* p = (const int*)ei;
        row = p[e];
        col = p[ne + e];
    }
    atomicOr(&g_A[row * NW + (col >> 5)], 1u << (col & 31));
    float v = 0.69314718055994531f * g_a0[col];
    long long q = __float2ll_rn(v * 4294967296.0f);
    atomicAdd((unsigned long long*)&g_stepq[row], (unsigned long long)q);
}

__global__ void finish_hop1_kernel() {
    int i = blockIdx.x * blockDim.x + threadIdx.x;
    if (i >= N) return;
    float s = (float)((double)g_stepq[i] * (1.0 / 4294967296.0));
    g_step[i] = s;
    g_a1[i]   = g_a0[i] + s;
}

// ---------------- fused boolmm + gated matvec --------------------------------
// 256 threads, HOP_G rows per block processed 2-at-a-time (p = tid>>7).
// vec staged in smem once per block; dense words use complement trick.
__global__ __launch_bounds__(256)
void fused_hop_kernel(int phase, float* __restrict__ out_final) {
    const unsigned* M   = phase ? g_A2  : g_A;
    const float*    vec = phase ? g_av2 : g_a1;

    const int tid = threadIdx.x;
    const int p   = tid >> 7;       // which of the 2 in-flight rows
    const int w   = tid & 127;      // word index
    const int i0  = blockIdx.x * HOP_G;

    __shared__ float          vsh[4096];
    __shared__ float          segsum[128];
    __shared__ float          psum[256];
    __shared__ unsigned short list[2][LISTCAP];
    __shared__ int            cnt[2];
    __shared__ float          part[8];

    // stage vec (16 floats/thread) + partial sums
    {
        float s = 0.f;
        #pragma unroll
        for (int q = 0; q < 4; q++) {
            float4 v = *(const float4*)&vec[tid * 16 + q * 4];
            *(float4*)&vsh[tid * 16 + q * 4] = v;
            s += (v.x + v.y) + (v.z + v.w);
        }
        psum[tid] = s;
    }
    __syncthreads();
    if (tid < 128) segsum[tid] = psum[2 * tid] + psum[2 * tid + 1];

    for (int pass = 0; pass < HOP_G / 2; pass++) {
        const int i = i0 + pass * 2 + p;
        if (w == 0) cnt[p] = 0;
        __syncthreads();

        // extract neighbor list of row i
        unsigned m0 = g_A[i * NW + w];
        int nb = __popc(m0);
        int pos = nb ? atomicAdd(&cnt[p], nb) : 0;
        {
            unsigned mt = m0;
            int jb = w * 32;
            while (mt && pos < LISTCAP) {
                int b = __ffs((int)mt) - 1;
                mt &= mt - 1;
                list[p][pos++] = (unsigned short)(jb + b);
            }
        }
        __syncthreads();

        const int c = min(cnt[p], LISTCAP);
        unsigned acc = 0u;
        int j = 0;
        for (; j + 4 <= c; j += 4) {
            unsigned q0 = __ldg(&M[(int)list[p][j]     * NW + w]);
            unsigned q1 = __ldg(&M[(int)list[p][j + 1] * NW + w]);
            unsigned q2 = __ldg(&M[(int)list[p][j + 2] * NW + w]);
            unsigned q3 = __ldg(&M[(int)list[p][j + 3] * NW + w]);
            acc |= (q0 | q1) | (q2 | q3);
        }
        for (; j < c; j++) acc |= __ldg(&M[(int)list[p][j] * NW + w]);

        if (cnt[p] > LISTCAP) {          // overflow fallback (OR is idempotent)
            for (int ww = 0; ww < NW; ww++) {
                unsigned mm = __ldg(&g_A[i * NW + ww]);
                int jb = ww * 32;
                while (mm) {
                    int b = __ffs((int)mm) - 1;
                    mm &= mm - 1;
                    acc |= __ldg(&M[(jb + b) * NW + w]);
                }
            }
        }

        if (!phase) g_A2[i * NW + w] = acc;

        // gated sum over set bits of vsh segment w
        float s;
        const float* base = vsh + w * 32;
        int pc = __popc(acc);
        if (pc > 16) {
            s = segsum[w];
            unsigned m = ~acc;
            while (m) {
                int b = __ffs((int)m) - 1;
                m &= m - 1;
                s -= base[b];
            }
        } else {
            s = 0.f;
            unsigned m = acc;
            while (m) {
                int b = __ffs((int)m) - 1;
                m &= m - 1;
                s += base[b];
            }
        }
        #pragma unroll
        for (int o = 16; o; o >>= 1) s += __shfl_down_sync(0xffffffffu, s, o);
        if ((tid & 31) == 0) part[tid >> 5] = s;
        __syncthreads();
        if (w == 0) {
            float tot = part[p * 4] + part[p * 4 + 1] + part[p * 4 + 2] + part[p * 4 + 3];
            if (!phase) {
                float ns = g_step[i] + 1.0986122886681098f * tot;   // ln 3
                g_step[i] = ns;
                g_av2[i]  = vec[i] + ns;
            } else {
                out_final[i] = vec[i] + g_step[i] + 1.3862943611198906f * tot; // ln 4
            }
        }
        __syncthreads();
    }
}

// ---------------- launch ----------------------------------------------------
extern "C" void kernel_launch(void* const* d_in, const int* in_sizes, int n_in,
                              void* d_out, int out_size) {
    const float* coeffs = (const float*)d_in[0];
    const void*  ei     = d_in[1];
    const float* W0     = (const float*)d_in[2];
    const float* b0     = (const float*)d_in[3];
    const float* W1     = (const float*)d_in[4];
    const float* W2     = (const float*)d_in[5];
    const float* W3     = (const float*)d_in[6];
    const float* b3     = (const float*)d_in[7];
    float* out = (float*)d_out;

    const int ne   = in_sizes[1] / 2;
    const int smem = (128 * 132 + 128 * 36) * (int)sizeof(float);  // 86016 B

    cudaFuncSetAttribute(gemm_kernel,
                         cudaFuncAttributeMaxDynamicSharedMemorySize, smem);

    float* Wt0; cudaGetSymbolAddress((void**)&Wt0, g_Wt);
    float* Wt1 = Wt0 + 16384;
    float* Wt2 = Wt0 + 32768;
    float* b0d; cudaGetSymbolAddress((void**)&b0d, g_buf0);
    float* b1d; cudaGetSymbolAddress((void**)&b1d, g_buf1);

    const int prep_blocks = (N * NW + 3 * 16384) / 256 + 1;
    prep_kernel<<<prep_blocks, 256>>>(W0, W1, W2, ei);

    gemm_kernel<<<N / GEMM_R, 256, smem>>>(coeffs, Wt0, b0,      b1d, nullptr, nullptr);
    gemm_kernel<<<N / GEMM_R, 256, smem>>>(b1d,    Wt1, nullptr, b0d, nullptr, nullptr);
    gemm_kernel<<<N / GEMM_R, 256, smem>>>(b0d,    Wt2, nullptr, nullptr, W3,  b3);

    edge_kernel<<<(ne + 255) / 256, 256>>>(ei, ne);
    finish_hop1_kernel<<<(N + 255) / 256, 256>>>();

    fused_hop_kernel<<<N / HOP_G, 256>>>(0, out);
    fused_hop_kernel<<<N / HOP_G, 256>>>(1, out);
}